// round 10
// baseline (speedup 1.0000x reference)
#include <cuda_runtime.h>
#include <cuda_fp16.h>
#include <cstdint>

#define NN 100000
#define NE 625000
#define DD 128
#define NL 10

// ---------------- scratch (device globals; no allocation allowed) ----------
static __device__ uint32_t g_pa[(size_t)NN * DD];    // ping (packed fp16 hi|lo)
static __device__ uint32_t g_pb[(size_t)NN * DD];    // pong
static __device__ __align__(16) unsigned short g_WT[(size_t)NL * 69632];
static __device__ float g_invdeg[NN];
static __device__ int   g_cnt[NN];
static __device__ int   g_fill[NN];
static __device__ int   g_rowptr[NN + 1];
static __device__ int   g_csr[NE];
static __device__ int   g_bsums[128];

// ---------------- PTX helpers ----------------------------------------------
__device__ __forceinline__ uint32_t smem_u32(const void* p) {
    uint32_t a;
    asm("{ .reg .u64 t; cvta.to.shared.u64 t, %1; cvt.u32.u64 %0, t; }"
        : "=r"(a) : "l"(p));
    return a;
}
__device__ __forceinline__ void ldsm_x4(uint32_t* r, uint32_t addr) {
    asm volatile("ldmatrix.sync.aligned.m8n8.x4.shared.b16 {%0,%1,%2,%3}, [%4];"
                 : "=r"(r[0]), "=r"(r[1]), "=r"(r[2]), "=r"(r[3]) : "r"(addr));
}
__device__ __forceinline__ void ldsm_x4t(uint32_t* r, uint32_t addr) {
    asm volatile("ldmatrix.sync.aligned.m8n8.x4.trans.shared.b16 {%0,%1,%2,%3}, [%4];"
                 : "=r"(r[0]), "=r"(r[1]), "=r"(r[2]), "=r"(r[3]) : "r"(addr));
}
__device__ __forceinline__ void mma_f32(float* d, const uint32_t* a,
                                        uint32_t b0, uint32_t b1) {
    asm volatile(
        "mma.sync.aligned.m16n8k16.row.col.f32.f16.f16.f32 "
        "{%0,%1,%2,%3}, {%4,%5,%6,%7}, {%8,%9}, {%0,%1,%2,%3};"
        : "+f"(d[0]), "+f"(d[1]), "+f"(d[2]), "+f"(d[3])
        : "r"(a[0]), "r"(a[1]), "r"(a[2]), "r"(a[3]), "r"(b0), "r"(b1));
}
__device__ __forceinline__ void mma_f16(uint32_t* d, const uint32_t* a,
                                        uint32_t b0, uint32_t b1) {
    asm volatile(
        "mma.sync.aligned.m16n8k16.row.col.f16.f16.f16.f16 "
        "{%0,%1}, {%2,%3,%4,%5}, {%6,%7}, {%0,%1};"
        : "+r"(d[0]), "+r"(d[1])
        : "r"(a[0]), "r"(a[1]), "r"(a[2]), "r"(a[3]), "r"(b0), "r"(b1));
}
#define BARS(id, n) asm volatile("bar.sync %0, %1;" :: "r"(id), "r"(n) : "memory")

// ---------------- CSR construction -----------------------------------------
__global__ void k_zero(void) {
    int i = blockIdx.x * blockDim.x + threadIdx.x;
    if (i < NN) { g_cnt[i] = 0; g_fill[i] = 0; }
}
__global__ void k_hist(const int* __restrict__ dst) {
    int e = blockIdx.x * blockDim.x + threadIdx.x;
    if (e < NE) atomicAdd(&g_cnt[dst[e]], 1);
}
#define SCAN_B 1024
__global__ void k_scan1(void) {
    __shared__ int sh[SCAN_B];
    int i = blockIdx.x * SCAN_B + threadIdx.x;
    int v = (i < NN) ? g_cnt[i] : 0;
    sh[threadIdx.x] = v;
    __syncthreads();
    for (int off = 1; off < SCAN_B; off <<= 1) {
        int t = (threadIdx.x >= off) ? sh[threadIdx.x - off] : 0;
        __syncthreads();
        sh[threadIdx.x] += t;
        __syncthreads();
    }
    if (i < NN) g_rowptr[i] = sh[threadIdx.x] - v;
    if (threadIdx.x == SCAN_B - 1) g_bsums[blockIdx.x] = sh[threadIdx.x];
}
__global__ void k_scan2(int nb) {
    __shared__ int sh[128];
    int v = (threadIdx.x < nb) ? g_bsums[threadIdx.x] : 0;
    sh[threadIdx.x] = v;
    __syncthreads();
    for (int off = 1; off < 128; off <<= 1) {
        int t = (threadIdx.x >= off) ? sh[threadIdx.x - off] : 0;
        __syncthreads();
        sh[threadIdx.x] += t;
        __syncthreads();
    }
    if (threadIdx.x < nb) g_bsums[threadIdx.x] = sh[threadIdx.x] - v;
}
__global__ void k_scan3(void) {
    int i = blockIdx.x * blockDim.x + threadIdx.x;
    if (i < NN) {
        g_rowptr[i] += g_bsums[i / SCAN_B];
        int c = g_cnt[i];
        g_invdeg[i] = 1.0f / (float)(c > 0 ? c : 1);
    }
    if (i == 0) g_rowptr[NN] = NE;
}
__global__ void k_scatter(const int* __restrict__ src, const int* __restrict__ dst) {
    int e = blockIdx.x * blockDim.x + threadIdx.x;
    if (e >= NE) return;
    int d = dst[e];
    int pos = atomicAdd(&g_fill[d], 1);
    g_csr[g_rowptr[d] + pos] = src[e];
}

// ---------------- fp32 <-> packed split-fp16 --------------------------------
__device__ __forceinline__ uint32_t packsplit(float v) {
    __half hb = __float2half_rn(v);
    float r = v - __half2float(hb);
    __half lb = __float2half_rn(r);
    return (uint32_t)__half_as_ushort(hb) |
           ((uint32_t)__half_as_ushort(lb) << 16);
}
__device__ __forceinline__ float unpacksum(uint32_t p) {
    float2 f = __half22float2(*(__half2*)&p);
    return f.x + f.y;
}

__global__ void k_split(const float* __restrict__ x, uint32_t* __restrict__ xp) {
    size_t i = ((size_t)blockIdx.x * blockDim.x + threadIdx.x) * 4;
    if (i >= (size_t)NN * DD) return;
    float4 v = *(const float4*)(x + i);
    uint4 o;
    o.x = packsplit(v.x); o.y = packsplit(v.y);
    o.z = packsplit(v.z); o.w = packsplit(v.w);
    *(uint4*)(xp + i) = o;
}

__global__ void k_wprep(const float* __restrict__ Wl, const float* __restrict__ Wr) {
    int idx = blockIdx.x * blockDim.x + threadIdx.x;
    if (idx >= NL * 256 * DD) return;
    int l = idx >> 15;
    int rem = idx & 32767;
    int k = rem >> 7;
    int n = rem & 127;
    float w = (k < 128) ? Wl[(size_t)l * 16384 + (size_t)k * 128 + n]
                        : Wr[(size_t)l * 16384 + (size_t)(k - 128) * 128 + n];
    uint32_t p = packsplit(w);
    size_t base = (size_t)l * 69632 + (size_t)k * 136 + n;
    g_WT[base] = (unsigned short)(p & 0xFFFF);
    g_WT[base + 34816] = (unsigned short)(p >> 16);
}

// ---------------- fused warp-specialized layer kernel -----------------------
// 640 threads: warps 0-15 MMA (tiles of 64 rows), warps 16-19 gather (cp.async
// mean-aggregation of the SAME tile directly into split-fp16 smem planes).
// Single aggbuf slot; named barriers: 1 = MMA-internal(512),
// 2 = FULL(640), 3 = EMPTY(640).
#define SMEM_W    0
#define W_PLANE   69632
#define SMEM_AGG  139264
#define SMEM_X    176128
#define SMEM_STG  194560
#define SMEM_BIAS 227328
#define SMEM_TOT  227840
#define A_BUF     9216
#define A_PAIR    18432

__global__ __launch_bounds__(640, 1)
void k_fused(const uint32_t* __restrict__ curp,
             const unsigned short* __restrict__ wt,
             const float* __restrict__ bias,
             uint32_t* __restrict__ outp,
             float* __restrict__ outf, int last) {
    extern __shared__ char smem[];
    const uint32_t sb = smem_u32(smem);
    const int tid = threadIdx.x;
    const int wid = tid >> 5, lane = tid & 31;
    const int nTiles = (NN + 63) / 64;

    {   // load W smem image (8704 uint4) + bias, all 640 threads
        const uint4* s4 = (const uint4*)wt;
        uint4* d4 = (uint4*)(smem + SMEM_W);
        #pragma unroll
        for (int i = 0; i < 14; i++) {
            int idx = tid + i * 640;
            if (idx < 8704) d4[idx] = s4[idx];
        }
        if (tid < 128) ((float*)(smem + SMEM_BIAS))[tid] = bias[tid];
    }
    __syncthreads();

    if (wid < 16) {
        // ================= MMA role =================
        const int warp_m = wid & 3, warp_n = wid >> 2;
        const uint32_t aOff = (uint32_t)(warp_m * 16 + (lane & 15)) * 144 +
                              (uint32_t)(lane >> 4) * 16;
        const uint32_t bBase = sb + SMEM_W +
            (uint32_t)(lane & 15) * 272 +
            (uint32_t)(warp_n * 32 + (lane >> 4) * 8) * 2;
        const int ldRow = tid >> 3;            // 0..63
        const int ldC = (tid & 7) * 8;
        const uint32_t stsH = sb + SMEM_X + (uint32_t)ldRow * 144 + (uint32_t)ldC * 2;

        uint4 pf[2];
        {   // prime: tile blockIdx, x chunk2 (cols 0..63)
            int row = blockIdx.x * 64 + ldRow;
            if ((int)blockIdx.x < nTiles && row < NN) {
                const uint4* p = (const uint4*)(curp + (size_t)row * DD + ldC);
                pf[0] = p[0]; pf[1] = p[1];
            } else { pf[0] = make_uint4(0,0,0,0); pf[1] = make_uint4(0,0,0,0); }
        }

        #define STS_PF() do {                                                   \
            uint4 q0 = pf[0], q1 = pf[1];                                       \
            uint4 hi, lo;                                                       \
            hi.x = __byte_perm(q0.x, q0.y, 0x5410);                             \
            hi.y = __byte_perm(q0.z, q0.w, 0x5410);                             \
            hi.z = __byte_perm(q1.x, q1.y, 0x5410);                             \
            hi.w = __byte_perm(q1.z, q1.w, 0x5410);                             \
            lo.x = __byte_perm(q0.x, q0.y, 0x7632);                             \
            lo.y = __byte_perm(q0.z, q0.w, 0x7632);                             \
            lo.z = __byte_perm(q1.x, q1.y, 0x7632);                             \
            lo.w = __byte_perm(q1.z, q1.w, 0x7632);                             \
            asm volatile("st.shared.v4.b32 [%0], {%1,%2,%3,%4};"                \
                :: "r"(stsH), "r"(hi.x), "r"(hi.y), "r"(hi.z), "r"(hi.w) : "memory"); \
            asm volatile("st.shared.v4.b32 [%0], {%1,%2,%3,%4};"                \
                :: "r"(stsH + A_BUF), "r"(lo.x), "r"(lo.y), "r"(lo.z), "r"(lo.w) : "memory"); \
        } while (0)

        #define CHUNK_COMPUTE(ABASE, CK) do {                                   \
            const uint32_t aH = (ABASE) + aOff;                                 \
            const uint32_t aL = aH + A_BUF;                                     \
            const uint32_t wH = bBase + (uint32_t)(CK) * 64 * 272;              \
            const uint32_t wL = wH + W_PLANE;                                   \
            _Pragma("unroll")                                                   \
            for (int ks = 0; ks < 4; ks++) {                                    \
                uint32_t wf[2][4];                                              \
                _Pragma("unroll")                                               \
                for (int nb = 0; nb < 2; nb++)                                  \
                    ldsm_x4t(wf[nb], wH + (uint32_t)ks * 4352 + (uint32_t)nb * 32); \
                uint32_t ah[4];                                                 \
                ldsm_x4(ah, aH + (uint32_t)ks * 32);                            \
                _Pragma("unroll")                                               \
                for (int nb = 0; nb < 2; nb++) {                                \
                    mma_f32(acc[nb * 2],     ah, wf[nb][0], wf[nb][1]);         \
                    mma_f32(acc[nb * 2 + 1], ah, wf[nb][2], wf[nb][3]);         \
                }                                                               \
                uint32_t al[4];                                                 \
                ldsm_x4(al, aL + (uint32_t)ks * 32);                            \
                _Pragma("unroll")                                               \
                for (int nb = 0; nb < 2; nb++) {                                \
                    mma_f16(accC[nb * 2],     al, wf[nb][0], wf[nb][1]);        \
                    mma_f16(accC[nb * 2 + 1], al, wf[nb][2], wf[nb][3]);        \
                }                                                               \
                uint32_t wg[2][4];                                              \
                _Pragma("unroll")                                               \
                for (int nb = 0; nb < 2; nb++)                                  \
                    ldsm_x4t(wg[nb], wL + (uint32_t)ks * 4352 + (uint32_t)nb * 32); \
                _Pragma("unroll")                                               \
                for (int nb = 0; nb < 2; nb++) {                                \
                    mma_f16(accC[nb * 2],     ah, wg[nb][0], wg[nb][1]);        \
                    mma_f16(accC[nb * 2 + 1], ah, wg[nb][2], wg[nb][3]);        \
                }                                                               \
            }                                                                   \
        } while (0)

        #pragma unroll 1
        for (int tile = blockIdx.x; tile < nTiles; tile += (int)gridDim.x) {
            const int rowBase = tile * 64;
            float acc[4][4];
            uint32_t accC[4][2];
            #pragma unroll
            for (int i = 0; i < 4; i++) {
                #pragma unroll
                for (int j = 0; j < 4; j++) acc[i][j] = 0.f;
                accC[i][0] = 0u; accC[i][1] = 0u;
            }

            BARS(2, 640);                       // FULL: aggbuf for this tile ready
            CHUNK_COMPUTE(sb + SMEM_AGG, 0);
            CHUNK_COMPUTE(sb + SMEM_AGG + A_PAIR, 1);
            BARS(3, 640);                       // EMPTY: gather may produce next

            BARS(1, 512);
            STS_PF();                           // x chunk2 -> xbuf
            {   // prefetch x chunk3 (cols 64..127)
                int row = rowBase + ldRow;
                if (row < NN) {
                    const uint4* p = (const uint4*)(curp + (size_t)row * DD + 64 + ldC);
                    pf[0] = p[0]; pf[1] = p[1];
                } else { pf[0] = make_uint4(0,0,0,0); pf[1] = make_uint4(0,0,0,0); }
            }
            BARS(1, 512);
            CHUNK_COMPUTE(sb + SMEM_X, 2);
            BARS(1, 512);
            STS_PF();                           // x chunk3 -> xbuf
            {   // prefetch next tile's x chunk2
                int nt = tile + (int)gridDim.x;
                int row = nt * 64 + ldRow;
                if (nt < nTiles && row < NN) {
                    const uint4* p = (const uint4*)(curp + (size_t)row * DD + ldC);
                    pf[0] = p[0]; pf[1] = p[1];
                } else { pf[0] = make_uint4(0,0,0,0); pf[1] = make_uint4(0,0,0,0); }
            }
            BARS(1, 512);
            CHUNK_COMPUTE(sb + SMEM_X, 3);

            // ---- epilogue ----
            const float* bs = (const float*)(smem + SMEM_BIAS);
            const int colBase = warp_n * 32 + (lane & 3) * 2;
            const int rBase = rowBase + warp_m * 16 + (lane >> 2);
            #pragma unroll
            for (int j = 0; j < 4; j++) {
                const int col = colBase + j * 8;
                const float b0 = bs[col], b1 = bs[col + 1];
                float2 c0 = __half22float2(*(__half2*)&accC[j][0]);
                float2 c1 = __half22float2(*(__half2*)&accC[j][1]);
                float vv[4];
                vv[0] = acc[j][0] + c0.x + b0;
                vv[1] = acc[j][1] + c0.y + b1;
                vv[2] = acc[j][2] + c1.x + b0;
                vv[3] = acc[j][3] + c1.y + b1;
                #pragma unroll
                for (int rr = 0; rr < 2; rr++) {
                    const int row = rBase + rr * 8;
                    if (row < NN) {
                        float v0 = vv[rr * 2], v1 = vv[rr * 2 + 1];
                        if (last) {
                            *(float2*)(outf + (size_t)row * DD + col) =
                                make_float2(v0, v1);
                        } else {
                            v0 = fmaxf(v0, 0.f); v1 = fmaxf(v1, 0.f);
                            uint2 o;
                            o.x = packsplit(v0);
                            o.y = packsplit(v1);
                            *(uint2*)(outp + (size_t)row * DD + col) = o;
                        }
                    }
                }
            }
        }
        #undef CHUNK_COMPUTE
        #undef STS_PF
    } else {
        // ================= gather role (warps 16-19) =================
        const int gw = wid - 16;
        const uint32_t stg = sb + SMEM_STG + (uint32_t)gw * 8192;
        bool hadTile = false;

        #pragma unroll 1
        for (int tile = blockIdx.x; tile < nTiles; tile += (int)gridDim.x) {
            if (hadTile) BARS(3, 640);          // EMPTY: wait consumers
            hadTile = true;

            const int r0 = tile * 64 + gw * 16;
            const int rc0 = (r0 < NN) ? r0 : NN;
            const int rc1 = (r0 + 16 < NN) ? (r0 + 16) : NN;
            const int eBeg = g_rowptr[rc0];
            const int eEnd = g_rowptr[rc1];
            const int total = eEnd - eBeg;

            int kIss = 0, kRed = 0, jR = 0;
            int nodeEndRel = ((r0 < NN) ? g_rowptr[r0 + 1] : eEnd) - eBeg;
            float4 acc = make_float4(0.f, 0.f, 0.f, 0.f);
            uint32_t idxReg = 0;

            #pragma unroll 1
            while (jR < 16) {
                // issue side: keep exactly 12 rows in flight
                while (kIss < kRed + 12 && kIss < total) {
                    if ((kIss & 31) == 0) {
                        int e = eBeg + kIss + lane;
                        idxReg = (e < eEnd) ? (uint32_t)g_csr[e] : 0u;
                    }
                    uint32_t srcn = __shfl_sync(0xFFFFFFFFu, idxReg, kIss & 31);
                    uint32_t dst = stg + (uint32_t)(kIss & 15) * 512 +
                                   (uint32_t)lane * 16;
                    const void* gsrc =
                        (const void*)(curp + (size_t)srcn * DD + lane * 4);
                    asm volatile("cp.async.cg.shared.global [%0], [%1], 16;"
                                 :: "r"(dst), "l"(gsrc) : "memory");
                    asm volatile("cp.async.commit_group;" ::: "memory");
                    kIss++;
                }
                if (kRed == nodeEndRel) {
                    // finalize node jR
                    int grow = r0 + jR;
                    float sc = (grow < NN) ? g_invdeg[grow] : 0.f;
                    uint32_t p0 = packsplit(acc.x * sc), p1 = packsplit(acc.y * sc);
                    uint32_t p2 = packsplit(acc.z * sc), p3 = packsplit(acc.w * sc);
                    uint32_t hi01 = __byte_perm(p0, p1, 0x5410);
                    uint32_t hi23 = __byte_perm(p2, p3, 0x5410);
                    uint32_t lo01 = __byte_perm(p0, p1, 0x7632);
                    uint32_t lo23 = __byte_perm(p2, p3, 0x7632);
                    uint32_t dH = sb + SMEM_AGG + (uint32_t)(lane >> 4) * A_PAIR +
                                  (uint32_t)(gw * 16 + jR) * 144 +
                                  (uint32_t)(lane & 15) * 8;
                    asm volatile("st.shared.v2.b32 [%0], {%1,%2};"
                                 :: "r"(dH), "r"(hi01), "r"(hi23) : "memory");
                    asm volatile("st.shared.v2.b32 [%0], {%1,%2};"
                                 :: "r"(dH + A_BUF), "r"(lo01), "r"(lo23) : "memory");
                    acc = make_float4(0.f, 0.f, 0.f, 0.f);
                    jR++;
                    if (jR < 16) {
                        int rn = r0 + jR;
                        nodeEndRel = ((rn < NN) ? g_rowptr[rn + 1] : eEnd) - eBeg;
                    }
                    continue;
                }
                // reduce one row
                if (kIss < total) {
                    asm volatile("cp.async.wait_group 11;" ::: "memory");
                } else {
                    asm volatile("cp.async.wait_group 0;" ::: "memory");
                }
                uint32_t saddr = stg + (uint32_t)(kRed & 15) * 512 +
                                 (uint32_t)lane * 16;
                uint32_t v0, v1, v2, v3;
                asm volatile("ld.shared.v4.b32 {%0,%1,%2,%3}, [%4];"
                             : "=r"(v0), "=r"(v1), "=r"(v2), "=r"(v3) : "r"(saddr));
                acc.x += unpacksum(v0); acc.y += unpacksum(v1);
                acc.z += unpacksum(v2); acc.w += unpacksum(v3);
                kRed++;
            }
            BARS(2, 640);                       // FULL: tile's aggbuf ready
        }
        if (hadTile) BARS(3, 640);              // match MMA's final EMPTY
    }
}

// ---------------- host driver (graph-capturable) ----------------------------
extern "C" void kernel_launch(void* const* d_in, const int* in_sizes, int n_in,
                              void* d_out, int out_size) {
    const float* x  = (const float*)d_in[0];
    const float* Wl = (const float*)d_in[1];
    const float* Wr = (const float*)d_in[2];
    const float* b  = (const float*)d_in[3];
    const int* ei   = (const int*)d_in[4];
    const int* src  = ei;
    const int* dst  = ei + NE;

    uint32_t *pa, *pb;
    unsigned short* wt;
    cudaGetSymbolAddress((void**)&pa, g_pa);
    cudaGetSymbolAddress((void**)&pb, g_pb);
    cudaGetSymbolAddress((void**)&wt, g_WT);

    cudaFuncSetAttribute(k_fused, cudaFuncAttributeMaxDynamicSharedMemorySize, SMEM_TOT);

    const int NB_SCAN = (NN + SCAN_B - 1) / SCAN_B;

    k_zero<<<(NN + 255) / 256, 256>>>();
    k_hist<<<(NE + 255) / 256, 256>>>(dst);
    k_scan1<<<NB_SCAN, SCAN_B>>>();
    k_scan2<<<1, 128>>>(NB_SCAN);
    k_scan3<<<(NN + 255) / 256, 256>>>();
    k_scatter<<<(NE + 255) / 256, 256>>>(src, dst);
    k_split<<<(NN * DD / 4 + 255) / 256, 256>>>(x, pa);
    k_wprep<<<(NL * 256 * DD + 255) / 256, 256>>>(Wl, Wr);

    uint32_t *cur = pa, *nxt = pb;
    for (int i = 0; i < NL; i++) {
        int last = (i == NL - 1) ? 1 : 0;
        k_fused<<<152, 640, SMEM_TOT>>>(cur,
                                        wt + (size_t)i * 69632,
                                        b + (size_t)i * DD,
                                        nxt, (float*)d_out, last);
        uint32_t* t = cur; cur = nxt; nxt = t;
    }
}

// round 12
// speedup vs baseline: 2.3924x; 2.3924x over previous
#include <cuda_runtime.h>
#include <cuda_fp16.h>
#include <cstdint>

#define NN 100000
#define NE 625000
#define DD 128
#define NL 10

// ---------------- scratch (device globals; no allocation allowed) ----------
// activations: fp16 hi plane (exact) + e4m3 lo plane (residual * 256)
static __device__ unsigned short g_ha[(size_t)NN * DD];   // ping hi
static __device__ unsigned char  g_l8a[(size_t)NN * DD];  // ping lo8
static __device__ unsigned short g_hb[(size_t)NN * DD];   // pong hi
static __device__ unsigned char  g_l8b[(size_t)NN * DD];  // pong lo8
static __device__ unsigned short g_gah[(size_t)NN * DD];  // agg hi
static __device__ unsigned char  g_gal8[(size_t)NN * DD]; // agg lo8
// pre-split W smem image: per layer [2 planes][256 k][136 cols (272B rows)]
static __device__ __align__(16) unsigned short g_WT[(size_t)NL * 69632];
static __device__ float g_invdeg[NN];
static __device__ int   g_cnt[NN];
static __device__ int   g_fill[NN];
static __device__ int   g_rowptr[NN + 1];
static __device__ int   g_csr[NE];
static __device__ int   g_bsums[128];

// ---------------- PTX helpers ----------------------------------------------
__device__ __forceinline__ uint32_t smem_u32(const void* p) {
    uint32_t a;
    asm("{ .reg .u64 t; cvta.to.shared.u64 t, %1; cvt.u32.u64 %0, t; }"
        : "=r"(a) : "l"(p));
    return a;
}
__device__ __forceinline__ void ldsm_x4(uint32_t* r, uint32_t addr) {
    asm volatile("ldmatrix.sync.aligned.m8n8.x4.shared.b16 {%0,%1,%2,%3}, [%4];"
                 : "=r"(r[0]), "=r"(r[1]), "=r"(r[2]), "=r"(r[3]) : "r"(addr));
}
__device__ __forceinline__ void ldsm_x4t(uint32_t* r, uint32_t addr) {
    asm volatile("ldmatrix.sync.aligned.m8n8.x4.trans.shared.b16 {%0,%1,%2,%3}, [%4];"
                 : "=r"(r[0]), "=r"(r[1]), "=r"(r[2]), "=r"(r[3]) : "r"(addr));
}
__device__ __forceinline__ void mma_f32(float* d, const uint32_t* a,
                                        uint32_t b0, uint32_t b1) {
    asm volatile(
        "mma.sync.aligned.m16n8k16.row.col.f32.f16.f16.f32 "
        "{%0,%1,%2,%3}, {%4,%5,%6,%7}, {%8,%9}, {%0,%1,%2,%3};"
        : "+f"(d[0]), "+f"(d[1]), "+f"(d[2]), "+f"(d[3])
        : "r"(a[0]), "r"(a[1]), "r"(a[2]), "r"(a[3]), "r"(b0), "r"(b1));
}
__device__ __forceinline__ void mma_f16(uint32_t* d, const uint32_t* a,
                                        uint32_t b0, uint32_t b1) {
    asm volatile(
        "mma.sync.aligned.m16n8k16.row.col.f16.f16.f16.f16 "
        "{%0,%1}, {%2,%3,%4,%5}, {%6,%7}, {%0,%1};"
        : "+r"(d[0]), "+r"(d[1])
        : "r"(a[0]), "r"(a[1]), "r"(a[2]), "r"(a[3]), "r"(b0), "r"(b1));
}
__device__ __forceinline__ unsigned short f16x2_to_e4m3x2(uint32_t h2) {
    unsigned short r;
    asm("cvt.rn.satfinite.e4m3x2.f16x2 %0, %1;" : "=h"(r) : "r"(h2));
    return r;
}
__device__ __forceinline__ uint32_t e4m3x2_to_f16x2(unsigned short b) {
    uint32_t r;
    asm("cvt.rn.f16x2.e4m3x2 %0, %1;" : "=r"(r) : "h"(b));
    return r;
}

// ---------------- CSR construction -----------------------------------------
__global__ void k_zero(void) {
    int i = blockIdx.x * blockDim.x + threadIdx.x;
    if (i < NN) { g_cnt[i] = 0; g_fill[i] = 0; }
}
__global__ void k_hist(const int* __restrict__ dst) {
    int e = blockIdx.x * blockDim.x + threadIdx.x;
    if (e < NE) atomicAdd(&g_cnt[dst[e]], 1);
}
#define SCAN_B 1024
__global__ void k_scan1(void) {
    __shared__ int sh[SCAN_B];
    int i = blockIdx.x * SCAN_B + threadIdx.x;
    int v = (i < NN) ? g_cnt[i] : 0;
    sh[threadIdx.x] = v;
    __syncthreads();
    for (int off = 1; off < SCAN_B; off <<= 1) {
        int t = (threadIdx.x >= off) ? sh[threadIdx.x - off] : 0;
        __syncthreads();
        sh[threadIdx.x] += t;
        __syncthreads();
    }
    if (i < NN) g_rowptr[i] = sh[threadIdx.x] - v;
    if (threadIdx.x == SCAN_B - 1) g_bsums[blockIdx.x] = sh[threadIdx.x];
}
__global__ void k_scan2(int nb) {
    __shared__ int sh[128];
    int v = (threadIdx.x < nb) ? g_bsums[threadIdx.x] : 0;
    sh[threadIdx.x] = v;
    __syncthreads();
    for (int off = 1; off < 128; off <<= 1) {
        int t = (threadIdx.x >= off) ? sh[threadIdx.x - off] : 0;
        __syncthreads();
        sh[threadIdx.x] += t;
        __syncthreads();
    }
    if (threadIdx.x < nb) g_bsums[threadIdx.x] = sh[threadIdx.x] - v;
}
__global__ void k_scan3(void) {
    int i = blockIdx.x * blockDim.x + threadIdx.x;
    if (i < NN) {
        g_rowptr[i] += g_bsums[i / SCAN_B];
        int c = g_cnt[i];
        g_invdeg[i] = 1.0f / (float)(c > 0 ? c : 1);
    }
    if (i == 0) g_rowptr[NN] = NE;
}
__global__ void k_scatter(const int* __restrict__ src, const int* __restrict__ dst) {
    int e = blockIdx.x * blockDim.x + threadIdx.x;
    if (e >= NE) return;
    int d = dst[e];
    int pos = atomicAdd(&g_fill[d], 1);
    g_csr[g_rowptr[d] + pos] = src[e];
}

// ---------------- fp32 <-> (fp16 hi, e4m3 lo*256) ---------------------------
// pack 2 values -> hi f16x2 (uint32) + lo e4m3x2 (ushort)
__device__ __forceinline__ void pack2v(float v0, float v1,
                                       uint32_t& hi2, unsigned short& lo2) {
    __half2 hv = __floats2half2_rn(v0, v1);
    float2 hf = __half22float2(hv);
    __half2 rv = __floats2half2_rn((v0 - hf.x) * 256.0f, (v1 - hf.y) * 256.0f);
    hi2 = *(uint32_t*)&hv;
    lo2 = f16x2_to_e4m3x2(*(uint32_t*)&rv);
}

__global__ void k_split(const float* __restrict__ x,
                        unsigned short* __restrict__ xh,
                        unsigned char* __restrict__ xl) {
    size_t i = ((size_t)blockIdx.x * blockDim.x + threadIdx.x) * 4;
    if (i >= (size_t)NN * DD) return;
    float4 v = *(const float4*)(x + i);
    uint32_t h01, h23; unsigned short l01, l23;
    pack2v(v.x, v.y, h01, l01);
    pack2v(v.z, v.w, h23, l23);
    uint2 ho; ho.x = h01; ho.y = h23;
    *(uint2*)(xh + i) = ho;
    *(uint32_t*)(xl + i) = (uint32_t)l01 | ((uint32_t)l23 << 16);
}

// ---------------- W pre-split (fp16 hi/lo planes, unchanged) -----------------
__global__ void k_wprep(const float* __restrict__ Wl, const float* __restrict__ Wr) {
    int idx = blockIdx.x * blockDim.x + threadIdx.x;
    if (idx >= NL * 256 * DD) return;
    int l = idx >> 15;
    int rem = idx & 32767;
    int k = rem >> 7;
    int n = rem & 127;
    float w = (k < 128) ? Wl[(size_t)l * 16384 + (size_t)k * 128 + n]
                        : Wr[(size_t)l * 16384 + (size_t)(k - 128) * 128 + n];
    __half hb = __float2half_rn(w);
    float r = w - __half2float(hb);
    __half lb = __float2half_rn(r);
    size_t base = (size_t)l * 69632 + (size_t)k * 136 + n;
    g_WT[base] = __half_as_ushort(hb);
    g_WT[base + 34816] = __half_as_ushort(lb);
}

// ---------------- mean aggregation (gather hi 8B + lo 4B per lane/edge) ------
__global__ void k_agg(const unsigned short* __restrict__ xh,
                      const unsigned char* __restrict__ xl,
                      unsigned short* __restrict__ ah,
                      unsigned char* __restrict__ al) {
    int node = blockIdx.x * 8 + (threadIdx.x >> 5);
    if (node >= NN) return;
    int lane = threadIdx.x & 31;
    int beg = g_rowptr[node];
    int end = g_rowptr[node + 1];
    float4 acch = make_float4(0.f, 0.f, 0.f, 0.f);
    float4 accl = make_float4(0.f, 0.f, 0.f, 0.f);
    #pragma unroll 1
    for (int t = beg; t < end; t++) {
        int s0 = g_csr[t];
        uint2 h = *(const uint2*)(xh + (size_t)s0 * DD + lane * 4);
        uint32_t l = *(const uint32_t*)(xl + (size_t)s0 * DD + lane * 4);
        float2 a0 = __half22float2(*(__half2*)&h.x);
        float2 a1 = __half22float2(*(__half2*)&h.y);
        uint32_t w0 = e4m3x2_to_f16x2((unsigned short)(l & 0xFFFF));
        uint32_t w1 = e4m3x2_to_f16x2((unsigned short)(l >> 16));
        float2 g0 = __half22float2(*(__half2*)&w0);
        float2 g1 = __half22float2(*(__half2*)&w1);
        acch.x += a0.x; acch.y += a0.y; acch.z += a1.x; acch.w += a1.y;
        accl.x += g0.x; accl.y += g0.y; accl.z += g1.x; accl.w += g1.y;
    }
    float sc = g_invdeg[node];
    float v0 = (acch.x + 0.00390625f * accl.x) * sc;
    float v1 = (acch.y + 0.00390625f * accl.y) * sc;
    float v2 = (acch.z + 0.00390625f * accl.z) * sc;
    float v3 = (acch.w + 0.00390625f * accl.w) * sc;
    uint32_t h01, h23; unsigned short l01, l23;
    pack2v(v0, v1, h01, l01);
    pack2v(v2, v3, h23, l23);
    uint2 ho; ho.x = h01; ho.y = h23;
    *(uint2*)(ah + (size_t)node * DD + lane * 4) = ho;
    *(uint32_t*)(al + (size_t)node * DD + lane * 4) =
        (uint32_t)l01 | ((uint32_t)l23 << 16);
}

// ---------------- persistent mma.sync GEMM (512 thr, M=64 tiles) ------------
// Y = [agg|x] @ [Wl;Wr] + b, split:
//   main AhWh (f32 acc); corrections: (Al*256)Wh -> accC1 (f16), AhWl -> accC2.
#define SMEM_W    0
#define W_PLANE   69632
#define SMEM_A    139264
#define A_BUF     9216           // one plane buffer: 64 rows * 144B
#define A_PAIR    18432          // hi+lo pair
#define SMEM_BIAS 176128
#define SMEM_TOT  176640

__global__ __launch_bounds__(512, 1)
void k_gemm_tc(const unsigned short* __restrict__ aggh,
               const unsigned char* __restrict__ aggl,
               const unsigned short* __restrict__ curh,
               const unsigned char* __restrict__ curl,
               const unsigned short* __restrict__ wt,
               const float* __restrict__ bias,
               unsigned short* __restrict__ outh,
               unsigned char* __restrict__ outl,
               float* __restrict__ outf, int last) {
    extern __shared__ char smem[];
    const uint32_t sb = smem_u32(smem);
    const int tid = threadIdx.x;
    const int wid = tid >> 5, lane = tid & 31;
    const int warp_m = wid & 3, warp_n = wid >> 2;   // 4x4

    {   // load W smem image (139264 B = 8704 uint4) + bias
        const uint4* s4 = (const uint4*)wt;
        uint4* d4 = (uint4*)(smem + SMEM_W);
        #pragma unroll
        for (int i = 0; i < 17; i++) d4[tid + i * 512] = s4[tid + i * 512];
        if (tid < 128) ((float*)(smem + SMEM_BIAS))[tid] = bias[tid];
    }
    __syncthreads();

    // ldmatrix bases
    const uint32_t aBase = sb + SMEM_A +
        (uint32_t)(warp_m * 16 + (lane & 15)) * 144 + (uint32_t)(lane >> 4) * 16;
    const uint32_t bBase = sb + SMEM_W +
        (uint32_t)(lane & 15) * 272 +
        (uint32_t)(warp_n * 32 + (lane >> 4) * 8) * 2;

    // loader coords: row = tid/8 (0..63), 8-col slab = (tid&7)*8
    const int ldRow = tid >> 3;
    const int ldC = (tid & 7) * 8;
    const uint32_t stsH = sb + SMEM_A + (uint32_t)ldRow * 144 + (uint32_t)ldC * 2;

    const int nTiles = (NN + 63) / 64;   // 1563
    uint4 pfh;
    uint2 pfl;

    // prologue prefetch: tile(blockIdx), chunk 0 (agg cols 0..63)
    {
        int row = blockIdx.x * 64 + ldRow;
        if ((int)blockIdx.x < nTiles && row < NN) {
            pfh = *(const uint4*)(aggh + (size_t)row * DD + ldC);
            pfl = *(const uint2*)(aggl + (size_t)row * DD + ldC);
        } else {
            pfh = make_uint4(0, 0, 0, 0);
            pfl = make_uint2(0, 0);
        }
    }

    for (int tile = blockIdx.x; tile < nTiles; tile += (int)gridDim.x) {
        const int rowBase = tile * 64;
        float acc[4][4];
        uint32_t accC1[4][2];   // (Al*256) . Wh
        uint32_t accC2[4][2];   // Ah . Wl
        #pragma unroll
        for (int i = 0; i < 4; i++) {
            #pragma unroll
            for (int j = 0; j < 4; j++) acc[i][j] = 0.f;
            accC1[i][0] = 0u; accC1[i][1] = 0u;
            accC2[i][0] = 0u; accC2[i][1] = 0u;
        }

        #pragma unroll 1
        for (int c = 0; c < 4; c++) {
            const int b = c & 1;
            // store prefetched chunk: hi direct, lo via e4m3->f16 cvt (keeps x256)
            {
                const uint32_t dH = stsH + (uint32_t)b * A_PAIR;
                const uint32_t dL = dH + A_BUF;
                asm volatile("st.shared.v4.b32 [%0], {%1,%2,%3,%4};"
                             :: "r"(dH), "r"(pfh.x), "r"(pfh.y), "r"(pfh.z), "r"(pfh.w) : "memory");
                uint32_t l0 = e4m3x2_to_f16x2((unsigned short)(pfl.x & 0xFFFF));
                uint32_t l1 = e4m3x2_to_f16x2((unsigned short)(pfl.x >> 16));
                uint32_t l2 = e4m3x2_to_f16x2((unsigned short)(pfl.y & 0xFFFF));
                uint32_t l3 = e4m3x2_to_f16x2((unsigned short)(pfl.y >> 16));
                asm volatile("st.shared.v4.b32 [%0], {%1,%2,%3,%4};"
                             :: "r"(dL), "r"(l0), "r"(l1), "r"(l2), "r"(l3) : "memory");
            }
            // prefetch next chunk (or next tile's chunk 0)
            {
                int nt = tile, nc = c + 1;
                if (nc == 4) { nt = tile + (int)gridDim.x; nc = 0; }
                if (nt < nTiles) {
                    const unsigned short* sh_ = (nc < 2) ? aggh : curh;
                    const unsigned char*  sl_ = (nc < 2) ? aggl : curl;
                    int row = nt * 64 + ldRow;
                    if (row < NN) {
                        size_t off = (size_t)row * DD + (nc & 1) * 64 + ldC;
                        pfh = *(const uint4*)(sh_ + off);
                        pfl = *(const uint2*)(sl_ + off);
                    } else {
                        pfh = make_uint4(0, 0, 0, 0);
                        pfl = make_uint2(0, 0);
                    }
                }
            }
            __syncthreads();

            // compute: main (f32 acc) + corrections (two f16 acc sets)
            const uint32_t aH = aBase + (uint32_t)b * A_PAIR;
            const uint32_t aL = aH + A_BUF;
            const uint32_t wH = bBase + (uint32_t)c * 64 * 272;
            const uint32_t wL = wH + W_PLANE;
            #pragma unroll
            for (int ks = 0; ks < 4; ks++) {
                uint32_t wf[2][4];
                #pragma unroll
                for (int nb = 0; nb < 2; nb++)
                    ldsm_x4t(wf[nb], wH + (uint32_t)ks * 4352 + (uint32_t)nb * 32);
                uint32_t ah[4];
                ldsm_x4(ah, aH + (uint32_t)ks * 32);
                #pragma unroll
                for (int nb = 0; nb < 2; nb++) {
                    mma_f32(acc[nb * 2],     ah, wf[nb][0], wf[nb][1]);
                    mma_f32(acc[nb * 2 + 1], ah, wf[nb][2], wf[nb][3]);
                }
                uint32_t al[4];
                ldsm_x4(al, aL + (uint32_t)ks * 32);
                #pragma unroll
                for (int nb = 0; nb < 2; nb++) {
                    mma_f16(accC1[nb * 2],     al, wf[nb][0], wf[nb][1]);
                    mma_f16(accC1[nb * 2 + 1], al, wf[nb][2], wf[nb][3]);
                }
                uint32_t wg[2][4];
                #pragma unroll
                for (int nb = 0; nb < 2; nb++)
                    ldsm_x4t(wg[nb], wL + (uint32_t)ks * 4352 + (uint32_t)nb * 32);
                #pragma unroll
                for (int nb = 0; nb < 2; nb++) {
                    mma_f16(accC2[nb * 2],     ah, wg[nb][0], wg[nb][1]);
                    mma_f16(accC2[nb * 2 + 1], ah, wg[nb][2], wg[nb][3]);
                }
            }
        }

        // ---- epilogue: merge corrections, bias (+relu), store ----
        const float* bs = (const float*)(smem + SMEM_BIAS);
        const int colBase = warp_n * 32 + (lane & 3) * 2;
        const int rBase = rowBase + warp_m * 16 + (lane >> 2);
        #pragma unroll
        for (int j = 0; j < 4; j++) {
            const int col = colBase + j * 8;
            const float b0 = bs[col], b1 = bs[col + 1];
            float2 s0 = __half22float2(*(__half2*)&accC1[j][0]);
            float2 s1 = __half22float2(*(__half2*)&accC1[j][1]);
            float2 t0 = __half22float2(*(__half2*)&accC2[j][0]);
            float2 t1 = __half22float2(*(__half2*)&accC2[j][1]);
            float vv[4];
            vv[0] = acc[j][0] + 0.00390625f * s0.x + t0.x + b0;
            vv[1] = acc[j][1] + 0.00390625f * s0.y + t0.y + b1;
            vv[2] = acc[j][2] + 0.00390625f * s1.x + t1.x + b0;
            vv[3] = acc[j][3] + 0.00390625f * s1.y + t1.y + b1;
            #pragma unroll
            for (int rr = 0; rr < 2; rr++) {
                const int row = rBase + rr * 8;
                if (row < NN) {
                    float v0 = vv[rr * 2], v1 = vv[rr * 2 + 1];
                    if (last) {
                        *(float2*)(outf + (size_t)row * DD + col) =
                            make_float2(v0, v1);
                    } else {
                        v0 = fmaxf(v0, 0.f); v1 = fmaxf(v1, 0.f);
                        uint32_t hw; unsigned short lw;
                        pack2v(v0, v1, hw, lw);
                        *(uint32_t*)(outh + (size_t)row * DD + col) = hw;
                        *(unsigned short*)(outl + (size_t)row * DD + col) = lw;
                    }
                }
            }
        }
    }
}

// ---------------- host driver (graph-capturable) ----------------------------
extern "C" void kernel_launch(void* const* d_in, const int* in_sizes, int n_in,
                              void* d_out, int out_size) {
    const float* x  = (const float*)d_in[0];
    const float* Wl = (const float*)d_in[1];
    const float* Wr = (const float*)d_in[2];
    const float* b  = (const float*)d_in[3];
    const int* ei   = (const int*)d_in[4];
    const int* src  = ei;
    const int* dst  = ei + NE;

    unsigned short *ha, *hb, *gah, *wt;
    unsigned char *l8a, *l8b, *gal8;
    cudaGetSymbolAddress((void**)&ha, g_ha);
    cudaGetSymbolAddress((void**)&hb, g_hb);
    cudaGetSymbolAddress((void**)&l8a, g_l8a);
    cudaGetSymbolAddress((void**)&l8b, g_l8b);
    cudaGetSymbolAddress((void**)&gah, g_gah);
    cudaGetSymbolAddress((void**)&gal8, g_gal8);
    cudaGetSymbolAddress((void**)&wt, g_WT);

    cudaFuncSetAttribute(k_gemm_tc, cudaFuncAttributeMaxDynamicSharedMemorySize, SMEM_TOT);

    const int NB_SCAN = (NN + SCAN_B - 1) / SCAN_B;

    k_zero<<<(NN + 255) / 256, 256>>>();
    k_hist<<<(NE + 255) / 256, 256>>>(dst);
    k_scan1<<<NB_SCAN, SCAN_B>>>();
    k_scan2<<<1, 128>>>(NB_SCAN);
    k_scan3<<<(NN + 255) / 256, 256>>>();
    k_scatter<<<(NE + 255) / 256, 256>>>(src, dst);
    k_split<<<(NN * DD / 4 + 255) / 256, 256>>>(x, ha, l8a);
    k_wprep<<<(NL * 256 * DD + 255) / 256, 256>>>(Wl, Wr);

    unsigned short *curh = ha, *nxth = hb;
    unsigned char *curl = l8a, *nxtl = l8b;
    for (int i = 0; i < NL; i++) {
        k_agg<<<(NN + 7) / 8, 256>>>(curh, curl, gah, gal8);
        int last = (i == NL - 1) ? 1 : 0;
        k_gemm_tc<<<152, 512, SMEM_TOT>>>(gah, gal8, curh, curl,
                                          wt + (size_t)i * 69632,
                                          b + (size_t)i * DD,
                                          nxth, nxtl, (float*)d_out, last);
        unsigned short* th = curh; curh = nxth; nxth = th;
        unsigned char*  tl = curl; curl = nxtl; nxtl = tl;
    }
}